// round 8
// baseline (speedup 1.0000x reference)
#include <cuda_runtime.h>
#include <cuda_fp16.h>
#include <cstdint>

#define MAXB 16384

// ---------------- scratch ----------------
__device__ __align__(16) __half g_B1h[512 * 512];        // [n][k] : t = gf @ B1^T
__device__ __align__(16) __half g_B3h[512 * 1024];       // [n][k] : k<512 pooled, k>=512 gf
__device__ __align__(16) float  g_ct[512];
__device__ __align__(16) float  g_bf3[512];
__device__ __align__(16) __half g_t16[(size_t)MAXB * 512];   // t (fp16)
__device__ __align__(16) __half g_X16[(size_t)MAXB * 512];   // pooled (fp16)
__device__ __align__(16) __half g_gf16[(size_t)MAXB * 512];  // gf (fp16)
__device__ __align__(16) float  g_lf[(size_t)MAXB * 512];

// ---------------- helpers ----------------
__device__ __forceinline__ uint32_t smem_u32(const void* p) {
    uint32_t a;
    asm("{ .reg .u64 t; cvta.to.shared.u64 t, %1; cvt.u32.u64 %0, t; }" : "=r"(a) : "l"(p));
    return a;
}
__device__ __forceinline__ void cp16s(uint32_t saddr, const void* src) {
    asm volatile("cp.async.cg.shared.global [%0], [%1], 16;" ::"r"(saddr), "l"(src));
}
__device__ __forceinline__ void ldm4(uint32_t r[4], uint32_t addr) {
    asm volatile("ldmatrix.sync.aligned.m8n8.x4.shared.b16 {%0,%1,%2,%3}, [%4];"
                 : "=r"(r[0]), "=r"(r[1]), "=r"(r[2]), "=r"(r[3]) : "r"(addr));
}
__device__ __forceinline__ void mma16(float c[4], const uint32_t a[4], const uint32_t b[2]) {
    asm volatile(
        "mma.sync.aligned.m16n8k16.row.col.f32.f16.f16.f32 "
        "{%0,%1,%2,%3},{%4,%5,%6,%7},{%8,%9},{%0,%1,%2,%3};"
        : "+f"(c[0]), "+f"(c[1]), "+f"(c[2]), "+f"(c[3])
        : "r"(a[0]), "r"(a[1]), "r"(a[2]), "r"(a[3]), "r"(b[0]), "r"(b[1]));
}

// ---------------- fused prep: conv(gf->fp16) + weight products + vectors ----------------
__global__ __launch_bounds__(256) void prep_all(const float* __restrict__ gf,
                                                int nconv,
                                                const float* __restrict__ Wq,
                                                const float* __restrict__ bq,
                                                const float* __restrict__ Wk,
                                                const float* __restrict__ Wv,
                                                const float* __restrict__ bv,
                                                const float* __restrict__ w_dr,
                                                const float* __restrict__ b_dr,
                                                const float* __restrict__ Wf,
                                                const float* __restrict__ bf) {
    int blk = blockIdx.x;
    if (blk < nconv) {
        int i = blk * 256 + threadIdx.x;
        float4 v = ((const float4*)gf)[i];
        ((__half2*)g_gf16)[i * 2 + 0] = __floats2half2_rn(v.x, v.y);
        ((__half2*)g_gf16)[i * 2 + 1] = __floats2half2_rn(v.z, v.w);
        return;
    }
    blk -= nconv;
    if (blk < 3072) {
        __shared__ float sA[16][17], sB[16][17];
        int tx = threadIdx.x & 15, ty = threadIdx.x >> 4;
        int job = blk >> 10, b2 = blk & 1023;
        int c0 = (b2 & 31) * 16, r0 = (b2 >> 5) * 16;
        float acc = 0.f;
        for (int h0 = 0; h0 < 256; h0 += 16) {
            if (job == 0) {
                sA[ty][tx] = Wk[(r0 + ty) * 256 + h0 + tx];
                sB[ty][tx] = Wq[(c0 + ty) * 256 + h0 + tx];
            } else if (job == 1) {
                sA[ty][tx] = Wf[(h0 + ty) * 512 + r0 + tx];
                sB[ty][tx] = Wv[(c0 + ty) * 256 + h0 + tx];
            } else {
                sA[ty][tx] = Wf[(256 + h0 + ty) * 512 + r0 + tx];
                sB[ty][tx] = Wv[(c0 + ty) * 256 + h0 + tx];
            }
            __syncthreads();
#pragma unroll
            for (int hh = 0; hh < 16; hh++) {
                if (job == 0) acc += sA[ty][hh] * sB[tx][hh];
                else          acc += sA[hh][ty] * sB[tx][hh];
            }
            __syncthreads();
        }
        if (job == 0) {
            g_B1h[(r0 + ty) * 512 + c0 + tx] = __float2half_rn(acc);
        } else if (job == 1) {
            g_B3h[(r0 + ty) * 1024 + c0 + tx] = __float2half_rn(acc);
        } else {
            float S = 0.f;
            for (int k = 0; k < 12; k++) S += w_dr[k];
            g_B3h[(r0 + ty) * 1024 + 512 + c0 + tx] = __float2half_rn(S * acc);
        }
    } else {
        int gid = (blk - 3072) * 256 + threadIdx.x;
        if (gid < 512) {
            float a = 0.f;
            for (int h = 0; h < 256; h++) a += bq[h] * Wk[gid * 256 + h];
            g_ct[gid] = a;
        } else if (gid < 1024) {
            int n = gid - 512;
            float S = 0.f;
            for (int k = 0; k < 12; k++) S += w_dr[k];
            float bd = b_dr[0];
            float a = bf[n];
            for (int h = 0; h < 256; h++) {
                a += bv[h] * Wf[h * 512 + n];
                a += (S * bv[h] + bd) * Wf[(256 + h) * 512 + n];
            }
            g_bf3[n] = a;
        }
    }
}

// ---------------- fp16 mma.sync GEMM, CTA 128x128, warp 64x32, K-chunk 64, 2-stage ----------------
// MODE 1: g_t16[B,512] = gf16 @ B1h^T + ct                        (K=512)
// MODE 3: out[B,512] = relu([X16|gf16] @ B3h^T + bf3) + lf + gf   (K=1024)
#define LDH2 72                          // padded halves per 64-K row (144 B stride)
#define BUF2 (128 * LDH2 * 2)            // 18432 B per operand per stage
#define SMEM_GEMM (4 * BUF2)             // 73728 B

template <int MODE>
__global__ __launch_bounds__(256, 2) void gemm_h(const float* __restrict__ gf,
                                                 float* __restrict__ out) {
    constexpr int KTOT = (MODE == 1) ? 512 : 1024;
    constexpr int KT = KTOT / 64;
    extern __shared__ __align__(16) char dsm[];
    const __half* Bt = (MODE == 1) ? g_B1h : g_B3h;

    int tid = threadIdx.x, lane = tid & 31, warp = tid >> 5;
    int wm = warp >> 2, wn = warp & 3;  // 2x4 warps -> warp tile 64(m) x 32(n)
    int m0 = blockIdx.y * 128, n0 = blockIdx.x * 128;

    uint32_t sb = smem_u32(dsm);
    uint32_t Ab[2] = {sb, sb + BUF2};
    uint32_t Bb[2] = {sb + 2 * BUF2, sb + 3 * BUF2};

    float acc[4][4][4];
#pragma unroll
    for (int i = 0; i < 4; i++)
#pragma unroll
        for (int j = 0; j < 4; j++)
#pragma unroll
            for (int q = 0; q < 4; q++) acc[i][j][q] = 0.f;

    int sr = tid >> 1;
    int hoff = (tid & 1) * 32;  // halves
    uint32_t dstoff = (uint32_t)(sr * LDH2 + hoff) * 2;

    int arow = (lane & 7) + ((lane >> 3) & 1) * 8;
    int acol = ((lane >> 4) & 1) * 8;
    uint32_t aoffB = (uint32_t)((wm * 64 + arow) * LDH2 + acol) * 2;
    int brow = (lane & 7) + ((lane >> 4) & 1) * 8;
    int bcol = ((lane >> 3) & 1) * 8;
    uint32_t boffB = (uint32_t)((wn * 32 + brow) * LDH2 + bcol) * 2;

    auto stage = [&](int c, int buf) {  // c = 64-K chunk index
        const __half* ar;
        if (MODE == 1) {
            ar = g_gf16 + (size_t)(m0 + sr) * 512 + c * 64 + hoff;
        } else {
            ar = (c < 8) ? (g_X16 + (size_t)(m0 + sr) * 512 + c * 64 + hoff)
                         : (g_gf16 + (size_t)(m0 + sr) * 512 + (c - 8) * 64 + hoff);
        }
        uint32_t ad = Ab[buf] + dstoff;
#pragma unroll
        for (int i = 0; i < 4; i++) cp16s(ad + i * 16, ar + i * 8);
        const __half* br = Bt + (size_t)(n0 + sr) * KTOT + c * 64 + hoff;
        uint32_t bd = Bb[buf] + dstoff;
#pragma unroll
        for (int i = 0; i < 4; i++) cp16s(bd + i * 16, br + i * 8);
        asm volatile("cp.async.commit_group;");
    };

    stage(0, 0);
    for (int kt = 0; kt < KT; kt++) {
        asm volatile("cp.async.wait_group 0;");
        __syncthreads();
        if (kt + 1 < KT) stage(kt + 1, (kt + 1) & 1);

        int cur = kt & 1;
#pragma unroll
        for (int kk = 0; kk < 4; kk++) {
            uint32_t af[4][4];
#pragma unroll
            for (int i = 0; i < 4; i++)
                ldm4(af[i], Ab[cur] + aoffB + (uint32_t)(i * 16 * LDH2 + kk * 16) * 2);
            uint32_t bfg[2][4];
#pragma unroll
            for (int j2 = 0; j2 < 2; j2++)
                ldm4(bfg[j2], Bb[cur] + boffB + (uint32_t)(j2 * 16 * LDH2 + kk * 16) * 2);
#pragma unroll
            for (int i = 0; i < 4; i++)
#pragma unroll
                for (int j = 0; j < 4; j++)
                    mma16(acc[i][j], af[i], &bfg[j >> 1][(j & 1) * 2]);
        }
    }

#pragma unroll
    for (int i = 0; i < 4; i++) {
        int row = m0 + wm * 64 + i * 16 + (lane >> 2);
#pragma unroll
        for (int j = 0; j < 4; j++) {
            int col = n0 + wn * 32 + j * 8 + (lane & 3) * 2;
#pragma unroll
            for (int h = 0; h < 2; h++) {
                int rr = row + h * 8;
                float v0 = acc[i][j][h * 2 + 0];
                float v1 = acc[i][j][h * 2 + 1];
                if (MODE == 1) {
                    ((__half2*)g_t16)[(size_t)rr * 256 + (col >> 1)] =
                        __floats2half2_rn(v0 + g_ct[col], v1 + g_ct[col + 1]);
                } else {
                    float2 lf = *(const float2*)&g_lf[(size_t)rr * 512 + col];
                    float2 gv = *(const float2*)&gf[(size_t)rr * 512 + col];
                    float z0 = fmaxf(v0 + g_bf3[col], 0.f) + lf.x + gv.x;
                    float z1 = fmaxf(v1 + g_bf3[col + 1], 0.f) + lf.y + gv.y;
                    *(float2*)&out[(size_t)rr * 512 + col] = make_float2(z0, z1);
                }
            }
        }
    }
}

// ---------------- attention + pooling + lf_mean (128 thr, float4, register-resident) ----------------
__global__ __launch_bounds__(128) void attn_pool(const float* __restrict__ local,
                                                 const float* __restrict__ w_dr,
                                                 const float* __restrict__ b_dr) {
    __shared__ float sred[12][4];
    __shared__ float a2s[12], wds[12];
    int b = blockIdx.x, tid = threadIdx.x, lane = tid & 31, warp = tid >> 5;
    const float4* lb4 = (const float4*)(local + (size_t)b * 12 * 512);

    if (tid < 12) wds[tid] = w_dr[tid];
    const __half2* tp = (const __half2*)g_t16 + (size_t)b * 256;
    float2 ta = __half22float2(tp[tid * 2]);
    float2 tb = __half22float2(tp[tid * 2 + 1]);

    float4 lv[12];
#pragma unroll
    for (int k = 0; k < 12; k++) lv[k] = lb4[k * 128 + tid];

    float p[12];
#pragma unroll
    for (int k = 0; k < 12; k++)
        p[k] = lv[k].x * ta.x + lv[k].y * ta.y + lv[k].z * tb.x + lv[k].w * tb.y;
#pragma unroll
    for (int k = 0; k < 12; k++)
#pragma unroll
        for (int off = 16; off; off >>= 1) p[k] += __shfl_xor_sync(0xffffffffu, p[k], off);
    if (lane == 0) {
#pragma unroll
        for (int k = 0; k < 12; k++) sred[k][warp] = p[k];
    }
    __syncthreads();
    if (tid < 32) {
        float v = -1e30f;
        if (lane < 12) {
            v = (sred[lane][0] + sred[lane][1]) + (sred[lane][2] + sred[lane][3]);
            v *= 0.0625f;  // 1/sqrt(256)
        }
        float m = v;
#pragma unroll
        for (int off = 16; off; off >>= 1) m = fmaxf(m, __shfl_xor_sync(0xffffffffu, m, off));
        float e = (lane < 12) ? __expf(v - m) : 0.f;
        float den = e;
#pragma unroll
        for (int off = 16; off; off >>= 1) den += __shfl_xor_sync(0xffffffffu, den, off);
        if (lane < 12) a2s[lane] = e / den;
    }
    __syncthreads();

    float bd = b_dr[0];
    float px = 0.f, py = 0.f, pz = 0.f, pw = 0.f;
    float lx = 0.f, ly = 0.f, lz = 0.f, lw = 0.f;
#pragma unroll
    for (int k = 0; k < 12; k++) {
        float a = a2s[k], w = wds[k];
        px += a * lv[k].x; py += a * lv[k].y; pz += a * lv[k].z; pw += a * lv[k].w;
        lx += w * lv[k].x; ly += w * lv[k].y; lz += w * lv[k].z; lw += w * lv[k].w;
    }
    __half2* xo = (__half2*)g_X16 + (size_t)b * 256;
    xo[tid * 2 + 0] = __floats2half2_rn(px, py);
    xo[tid * 2 + 1] = __floats2half2_rn(pz, pw);
    ((float4*)g_lf)[(size_t)b * 128 + tid] = make_float4(lx + bd, ly + bd, lz + bd, lw + bd);
}

extern "C" void kernel_launch(void* const* d_in, const int* in_sizes, int n_in,
                              void* d_out, int out_size) {
    const float* gf   = (const float*)d_in[0];
    const float* locl = (const float*)d_in[1];
    const float* Wq   = (const float*)d_in[2];
    const float* bq   = (const float*)d_in[3];
    const float* Wk   = (const float*)d_in[4];
    const float* Wv   = (const float*)d_in[6];
    const float* bv   = (const float*)d_in[7];
    const float* w_dr = (const float*)d_in[8];
    const float* b_dr = (const float*)d_in[9];
    const float* Wf   = (const float*)d_in[10];
    const float* bf   = (const float*)d_in[11];
    float* out = (float*)d_out;
    int B = in_sizes[0] / 512;

    cudaFuncSetAttribute(gemm_h<1>, cudaFuncAttributeMaxDynamicSharedMemorySize, SMEM_GEMM);
    cudaFuncSetAttribute(gemm_h<3>, cudaFuncAttributeMaxDynamicSharedMemorySize, SMEM_GEMM);

    int nconv = B * 512 / 4 / 256;
    prep_all<<<nconv + 3076, 256>>>(gf, nconv, Wq, bq, Wk, Wv, bv, w_dr, b_dr, Wf, bf);
    gemm_h<1><<<dim3(4, B / 128), 256, SMEM_GEMM>>>(gf, nullptr);
    attn_pool<<<B, 128>>>(locl, w_dr, b_dr);
    gemm_h<3><<<dim3(4, B / 128), 256, SMEM_GEMM>>>(gf, out);
}

// round 9
// speedup vs baseline: 1.0747x; 1.0747x over previous
#include <cuda_runtime.h>
#include <cuda_fp16.h>
#include <cstdint>

#define MAXB 16384

// ---------------- scratch ----------------
__device__ __align__(16) __half g_B1h[512 * 512];        // [n][k] : t = gf @ B1^T
__device__ __align__(16) __half g_B3h[512 * 1024];       // [n][k] : k<512 pooled, k>=512 gf
__device__ __align__(16) float  g_ct[512];
__device__ __align__(16) float  g_bf3[512];
__device__ __align__(16) __half g_t16[(size_t)MAXB * 512];   // t (fp16)
__device__ __align__(16) __half g_X16[(size_t)MAXB * 512];   // pooled (fp16)
__device__ __align__(16) __half g_gf16[(size_t)MAXB * 512];  // gf (fp16)
__device__ __align__(16) float  g_lf[(size_t)MAXB * 512];

// ---------------- helpers ----------------
__device__ __forceinline__ uint32_t smem_u32(const void* p) {
    uint32_t a;
    asm("{ .reg .u64 t; cvta.to.shared.u64 t, %1; cvt.u32.u64 %0, t; }" : "=r"(a) : "l"(p));
    return a;
}
__device__ __forceinline__ void cp16s(uint32_t saddr, const void* src) {
    asm volatile("cp.async.cg.shared.global [%0], [%1], 16;" ::"r"(saddr), "l"(src));
}
__device__ __forceinline__ void ldm4(uint32_t r[4], uint32_t addr) {
    asm volatile("ldmatrix.sync.aligned.m8n8.x4.shared.b16 {%0,%1,%2,%3}, [%4];"
                 : "=r"(r[0]), "=r"(r[1]), "=r"(r[2]), "=r"(r[3]) : "r"(addr));
}
__device__ __forceinline__ void mma16(float c[4], const uint32_t a[4], const uint32_t b[2]) {
    asm volatile(
        "mma.sync.aligned.m16n8k16.row.col.f32.f16.f16.f32 "
        "{%0,%1,%2,%3},{%4,%5,%6,%7},{%8,%9},{%0,%1,%2,%3};"
        : "+f"(c[0]), "+f"(c[1]), "+f"(c[2]), "+f"(c[3])
        : "r"(a[0]), "r"(a[1]), "r"(a[2]), "r"(a[3]), "r"(b[0]), "r"(b[1]));
}

// ---------------- fused prep: conv(gf->fp16) + weight products + vectors ----------------
__global__ __launch_bounds__(256) void prep_all(const float* __restrict__ gf,
                                                int nconv,
                                                const float* __restrict__ Wq,
                                                const float* __restrict__ bq,
                                                const float* __restrict__ Wk,
                                                const float* __restrict__ Wv,
                                                const float* __restrict__ bv,
                                                const float* __restrict__ w_dr,
                                                const float* __restrict__ b_dr,
                                                const float* __restrict__ Wf,
                                                const float* __restrict__ bf) {
    int blk = blockIdx.x;
    if (blk < nconv) {
        int i = blk * 256 + threadIdx.x;
        float4 v = ((const float4*)gf)[i];
        ((__half2*)g_gf16)[i * 2 + 0] = __floats2half2_rn(v.x, v.y);
        ((__half2*)g_gf16)[i * 2 + 1] = __floats2half2_rn(v.z, v.w);
        return;
    }
    blk -= nconv;
    if (blk < 3072) {
        __shared__ float sA[16][17], sB[16][17];
        int tx = threadIdx.x & 15, ty = threadIdx.x >> 4;
        int job = blk >> 10, b2 = blk & 1023;
        int c0 = (b2 & 31) * 16, r0 = (b2 >> 5) * 16;
        float acc = 0.f;
        for (int h0 = 0; h0 < 256; h0 += 16) {
            if (job == 0) {
                sA[ty][tx] = Wk[(r0 + ty) * 256 + h0 + tx];
                sB[ty][tx] = Wq[(c0 + ty) * 256 + h0 + tx];
            } else if (job == 1) {
                sA[ty][tx] = Wf[(h0 + ty) * 512 + r0 + tx];
                sB[ty][tx] = Wv[(c0 + ty) * 256 + h0 + tx];
            } else {
                sA[ty][tx] = Wf[(256 + h0 + ty) * 512 + r0 + tx];
                sB[ty][tx] = Wv[(c0 + ty) * 256 + h0 + tx];
            }
            __syncthreads();
#pragma unroll
            for (int hh = 0; hh < 16; hh++) {
                if (job == 0) acc += sA[ty][hh] * sB[tx][hh];
                else          acc += sA[hh][ty] * sB[tx][hh];
            }
            __syncthreads();
        }
        if (job == 0) {
            g_B1h[(r0 + ty) * 512 + c0 + tx] = __float2half_rn(acc);
        } else if (job == 1) {
            g_B3h[(r0 + ty) * 1024 + c0 + tx] = __float2half_rn(acc);
        } else {
            float S = 0.f;
            for (int k = 0; k < 12; k++) S += w_dr[k];
            g_B3h[(r0 + ty) * 1024 + 512 + c0 + tx] = __float2half_rn(S * acc);
        }
    } else {
        int gid = (blk - 3072) * 256 + threadIdx.x;
        if (gid < 512) {
            float a = 0.f;
            for (int h = 0; h < 256; h++) a += bq[h] * Wk[gid * 256 + h];
            g_ct[gid] = a;
        } else if (gid < 1024) {
            int n = gid - 512;
            float S = 0.f;
            for (int k = 0; k < 12; k++) S += w_dr[k];
            float bd = b_dr[0];
            float a = bf[n];
            for (int h = 0; h < 256; h++) {
                a += bv[h] * Wf[h * 512 + n];
                a += (S * bv[h] + bd) * Wf[(256 + h) * 512 + n];
            }
            g_bf3[n] = a;
        }
    }
}

// ---------------- fp16 mma.sync GEMM, CTA 64x128, warp 32x32, k-chunk 32, 3-stage ----------------
// MODE 1: g_t16[B,512] = gf16 @ B1h^T + ct                        (K=512)
// MODE 3: out[B,512] = relu([X16|gf16] @ B3h^T + bf3) + lf + gf   (K=1024)
#define LDH 40
#define ABUF (64 * LDH * 2)             // 5120 B
#define BBUF (128 * LDH * 2)            // 10240 B
#define SMEM_GEMM (3 * (ABUF + BBUF))   // 46080 B

template <int MODE>
__global__ __launch_bounds__(256, 3) void gemm_h(const float* __restrict__ gf,
                                                 float* __restrict__ out) {
    constexpr int KTOT = (MODE == 1) ? 512 : 1024;
    constexpr int KT = KTOT / 32;
    extern __shared__ __align__(16) char dsm[];
    const __half* Bt = (MODE == 1) ? g_B1h : g_B3h;

    int tid = threadIdx.x, lane = tid & 31, warp = tid >> 5;
    int wm = warp >> 2, wn = warp & 3;  // 2x4 warps -> warp tile 32(m) x 32(n)
    int m0 = blockIdx.y * 64, n0 = blockIdx.x * 128;

    uint32_t sb = smem_u32(dsm);
    uint32_t Ab[3], Bb[3];
#pragma unroll
    for (int s = 0; s < 3; s++) { Ab[s] = sb + s * ABUF; Bb[s] = sb + 3 * ABUF + s * BBUF; }

    float acc[2][4][4];
#pragma unroll
    for (int i = 0; i < 2; i++)
#pragma unroll
        for (int j = 0; j < 4; j++)
#pragma unroll
            for (int q = 0; q < 4; q++) acc[i][j][q] = 0.f;

    // staging maps: A 64 rows x 32 halves (1x16B per thread); B 128 rows x 32 halves (2x16B)
    int srA = tid >> 2;              // 0..63
    int hA = (tid & 3) * 8;          // halves
    uint32_t adst = (uint32_t)(srA * LDH + hA) * 2;
    int srB = tid >> 1;              // 0..127
    int hB = (tid & 1) * 16;         // halves
    uint32_t bdst = (uint32_t)(srB * LDH + hB) * 2;

    int arow = (lane & 7) + ((lane >> 3) & 1) * 8;
    int acol = ((lane >> 4) & 1) * 8;
    uint32_t aoffB = (uint32_t)((wm * 32 + arow) * LDH + acol) * 2;
    int brow = (lane & 7) + ((lane >> 4) & 1) * 8;
    int bcol = ((lane >> 3) & 1) * 8;
    uint32_t boffB = (uint32_t)((wn * 32 + brow) * LDH + bcol) * 2;

    auto stage = [&](int c, int buf) {
        const __half* ar;
        if (MODE == 1) {
            ar = g_gf16 + (size_t)(m0 + srA) * 512 + c * 32 + hA;
        } else {
            ar = (c < 16) ? (g_X16 + (size_t)(m0 + srA) * 512 + c * 32 + hA)
                          : (g_gf16 + (size_t)(m0 + srA) * 512 + (c - 16) * 32 + hA);
        }
        cp16s(Ab[buf] + adst, ar);
        const __half* br = Bt + (size_t)(n0 + srB) * KTOT + c * 32 + hB;
        cp16s(Bb[buf] + bdst, br);
        cp16s(Bb[buf] + bdst + 16, br + 8);
        asm volatile("cp.async.commit_group;");
    };

    stage(0, 0);
    stage(1, 1);
    for (int kt = 0; kt < KT; kt++) {
        if (kt < KT - 1) asm volatile("cp.async.wait_group 1;");
        else             asm volatile("cp.async.wait_group 0;");
        __syncthreads();
        if (kt + 2 < KT) stage(kt + 2, (kt + 2) % 3);

        int cur = kt % 3;
#pragma unroll
        for (int kk = 0; kk < 2; kk++) {
            uint32_t af[2][4];
#pragma unroll
            for (int i = 0; i < 2; i++)
                ldm4(af[i], Ab[cur] + aoffB + (uint32_t)(i * 16 * LDH + kk * 16) * 2);
            uint32_t bfg[2][4];
#pragma unroll
            for (int j2 = 0; j2 < 2; j2++)
                ldm4(bfg[j2], Bb[cur] + boffB + (uint32_t)(j2 * 16 * LDH + kk * 16) * 2);
#pragma unroll
            for (int i = 0; i < 2; i++)
#pragma unroll
                for (int j = 0; j < 4; j++)
                    mma16(acc[i][j], af[i], &bfg[j >> 1][(j & 1) * 2]);
        }
    }

#pragma unroll
    for (int i = 0; i < 2; i++) {
        int row = m0 + wm * 32 + i * 16 + (lane >> 2);
#pragma unroll
        for (int j = 0; j < 4; j++) {
            int col = n0 + wn * 32 + j * 8 + (lane & 3) * 2;
#pragma unroll
            for (int h = 0; h < 2; h++) {
                int rr = row + h * 8;
                float v0 = acc[i][j][h * 2 + 0];
                float v1 = acc[i][j][h * 2 + 1];
                if (MODE == 1) {
                    ((__half2*)g_t16)[(size_t)rr * 256 + (col >> 1)] =
                        __floats2half2_rn(v0 + g_ct[col], v1 + g_ct[col + 1]);
                } else {
                    float2 lf = *(const float2*)&g_lf[(size_t)rr * 512 + col];
                    float2 gv = *(const float2*)&gf[(size_t)rr * 512 + col];
                    float z0 = fmaxf(v0 + g_bf3[col], 0.f) + lf.x + gv.x;
                    float z1 = fmaxf(v1 + g_bf3[col + 1], 0.f) + lf.y + gv.y;
                    *(float2*)&out[(size_t)rr * 512 + col] = make_float2(z0, z1);
                }
            }
        }
    }
}

// ---------------- attention + pooling + lf_mean: 2 batch rows per 256-thr block ----------------
__global__ __launch_bounds__(256) void attn_pool(const float* __restrict__ local,
                                                 const float* __restrict__ w_dr,
                                                 const float* __restrict__ b_dr) {
    __shared__ float sred[2][12][4];
    __shared__ float a2s[2][12];
    __shared__ float wds[12];
    int tid = threadIdx.x, lane = tid & 31, warp = tid >> 5;
    int sub = tid >> 7;          // 0/1: which batch row
    int lt = tid & 127;          // thread within row
    int b = blockIdx.x * 2 + sub;
    const float4* lb4 = (const float4*)(local + (size_t)b * 12 * 512);

    if (tid < 12) wds[tid] = w_dr[tid];
    const __half2* tp = (const __half2*)g_t16 + (size_t)b * 256;
    float2 ta = __half22float2(tp[lt * 2]);
    float2 tb = __half22float2(tp[lt * 2 + 1]);

    float4 lv[12];
#pragma unroll
    for (int k = 0; k < 12; k++) lv[k] = lb4[k * 128 + lt];

    float p[12];
#pragma unroll
    for (int k = 0; k < 12; k++)
        p[k] = lv[k].x * ta.x + lv[k].y * ta.y + lv[k].z * tb.x + lv[k].w * tb.y;
#pragma unroll
    for (int k = 0; k < 12; k++)
#pragma unroll
        for (int off = 16; off; off >>= 1) p[k] += __shfl_xor_sync(0xffffffffu, p[k], off);
    if (lane == 0) {
#pragma unroll
        for (int k = 0; k < 12; k++) sred[sub][k][warp & 3] = p[k];
    }
    __syncthreads();
    if (lt < 32) {  // warp 0 handles row 0, warp 4 handles row 1
        float v = -1e30f;
        if (lane < 12) {
            v = (sred[sub][lane][0] + sred[sub][lane][1]) +
                (sred[sub][lane][2] + sred[sub][lane][3]);
            v *= 0.0625f;  // 1/sqrt(256)
        }
        float m = v;
#pragma unroll
        for (int off = 16; off; off >>= 1) m = fmaxf(m, __shfl_xor_sync(0xffffffffu, m, off));
        float e = (lane < 12) ? __expf(v - m) : 0.f;
        float den = e;
#pragma unroll
        for (int off = 16; off; off >>= 1) den += __shfl_xor_sync(0xffffffffu, den, off);
        if (lane < 12) a2s[sub][lane] = e / den;
    }
    __syncthreads();

    float bd = b_dr[0];
    float px = 0.f, py = 0.f, pz = 0.f, pw = 0.f;
    float lx = 0.f, ly = 0.f, lz = 0.f, lw = 0.f;
#pragma unroll
    for (int k = 0; k < 12; k++) {
        float a = a2s[sub][k], w = wds[k];
        px += a * lv[k].x; py += a * lv[k].y; pz += a * lv[k].z; pw += a * lv[k].w;
        lx += w * lv[k].x; ly += w * lv[k].y; lz += w * lv[k].z; lw += w * lv[k].w;
    }
    __half2* xo = (__half2*)g_X16 + (size_t)b * 256;
    xo[lt * 2 + 0] = __floats2half2_rn(px, py);
    xo[lt * 2 + 1] = __floats2half2_rn(pz, pw);
    ((float4*)g_lf)[(size_t)b * 128 + lt] = make_float4(lx + bd, ly + bd, lz + bd, lw + bd);
}

extern "C" void kernel_launch(void* const* d_in, const int* in_sizes, int n_in,
                              void* d_out, int out_size) {
    const float* gf   = (const float*)d_in[0];
    const float* locl = (const float*)d_in[1];
    const float* Wq   = (const float*)d_in[2];
    const float* bq   = (const float*)d_in[3];
    const float* Wk   = (const float*)d_in[4];
    const float* Wv   = (const float*)d_in[6];
    const float* bv   = (const float*)d_in[7];
    const float* w_dr = (const float*)d_in[8];
    const float* b_dr = (const float*)d_in[9];
    const float* Wf   = (const float*)d_in[10];
    const float* bf   = (const float*)d_in[11];
    float* out = (float*)d_out;
    int B = in_sizes[0] / 512;

    cudaFuncSetAttribute(gemm_h<1>, cudaFuncAttributeMaxDynamicSharedMemorySize, SMEM_GEMM);
    cudaFuncSetAttribute(gemm_h<3>, cudaFuncAttributeMaxDynamicSharedMemorySize, SMEM_GEMM);

    int nconv = B * 512 / 4 / 256;
    prep_all<<<nconv + 3076, 256>>>(gf, nconv, Wq, bq, Wk, Wv, bv, w_dr, b_dr, Wf, bf);
    gemm_h<1><<<dim3(4, B / 64), 256, SMEM_GEMM>>>(gf, nullptr);
    attn_pool<<<B / 2, 256>>>(locl, w_dr, b_dr);
    gemm_h<3><<<dim3(4, B / 64), 256, SMEM_GEMM>>>(gf, out);
}